// round 1
// baseline (speedup 1.0000x reference)
#include <cuda_runtime.h>

#define KK 16
#define LL 64
#define BB 32768

__global__ __launch_bounds__(128) void bitop_kernel(
    const float* __restrict__ op1, const float* __restrict__ op2,
    float* __restrict__ out)
{
    const int b = blockIdx.x * blockDim.x + threadIdx.x;
    if (b >= BB) return;

    const float4* p1 = reinterpret_cast<const float4*>(op1) + (size_t)b * (LL * KK / 4);
    const float4* p2 = reinterpret_cast<const float4*>(op2) + (size_t)b * (LL * KK / 4);
    float4* oadd = reinterpret_cast<float4*>(out)                        + (size_t)b * (LL * KK / 4);
    float4* osub = reinterpret_cast<float4*>(out + (size_t)BB * LL * KK) + (size_t)b * (LL * KK / 4);

    float carry0 = 1.f, carry1 = 0.f;
    float borrow0 = 1.f, borrow1 = 0.f;

    // software pipeline: preload digit 0
    float4 A0 = p1[0], A1 = p1[1], A2 = p1[2], A3 = p1[3];
    float4 B0 = p2[0], B1 = p2[1], B2 = p2[2], B3 = p2[3];

    #pragma unroll 1
    for (int l = 0; l < LL; ++l) {
        float a[16] = {A0.x, A0.y, A0.z, A0.w,
                       A1.x, A1.y, A1.z, A1.w,
                       A2.x, A2.y, A2.z, A2.w,
                       A3.x, A3.y, A3.z, A3.w};
        float c[16] = {B0.x, B0.y, B0.z, B0.w,
                       B1.x, B1.y, B1.z, B1.w,
                       B2.x, B2.y, B2.z, B2.w,
                       B3.x, B3.y, B3.z, B3.w};

        // prefetch next digit while computing this one
        if (l < LL - 1) {
            const int o = (l + 1) * 4;
            A0 = p1[o]; A1 = p1[o + 1]; A2 = p1[o + 2]; A3 = p1[o + 3];
            B0 = p2[o]; B1 = p2[o + 1]; B2 = p2[o + 2]; B3 = p2[o + 3];
        }

        // P[s] = sum_{i+j=s} a_i c_j   (s in 0..30)
        // D[t] = sum_{i-j=t-15} a_i c_j (t in 0..30)
        float P[31], D[31];
        #pragma unroll
        for (int s = 0; s < 31; ++s) { P[s] = 0.f; D[s] = 0.f; }

        #pragma unroll
        for (int i = 0; i < 16; ++i) {
            #pragma unroll
            for (int j = 0; j < 16; ++j) {
                P[i + j]      = fmaf(a[i], c[j], P[i + j]);
                D[i - j + 15] = fmaf(a[i], c[j], D[i - j + 15]);
            }
        }

        // prefix/suffix sums for carry/borrow update
        float SL = 0.f, SH = 0.f, DL = 0.f, DH = 0.f;
        #pragma unroll
        for (int s = 0; s < 15; ++s)  SL += P[s];
        #pragma unroll
        for (int s = 16; s < 31; ++s) SH += P[s];
        #pragma unroll
        for (int t = 0; t < 15; ++t)  DL += D[t];
        #pragma unroll
        for (int t = 16; t < 31; ++t) DH += D[t];

        float addr[16], subr[16];
        #pragma unroll
        for (int v = 0; v < 16; ++v) {
            // add: c=0 -> s = v or v+16 (v<=14); c=1 -> s = v-1 (v>=1) or v+15
            const float a0 = P[v] + ((v < 15) ? P[v + 16] : 0.f);
            const float a1 = ((v >= 1) ? P[v - 1] : 0.f) + P[v + 15];
            addr[v] = carry0 * a0 + carry1 * a1;
            // sub: c=0 -> t = v+15 or v-1 (v>=1); c=1 -> t = v+16 (v<=14) or v
            const float s0 = D[v + 15] + ((v >= 1) ? D[v - 1] : 0.f);
            const float s1 = ((v <= 14) ? D[v + 16] : 0.f) + D[v];
            subr[v] = borrow0 * s0 + borrow1 * s1;
        }

        // state updates (use old carry/borrow)
        const float nc1 = carry0 * SH + carry1 * (P[15] + SH);
        const float nc0 = carry0 * (SL + P[15]) + carry1 * SL;
        const float nb1 = borrow0 * DL + borrow1 * (DL + D[15]);
        const float nb0 = borrow0 * (D[15] + DH) + borrow1 * DH;
        carry0 = nc0; carry1 = nc1;
        borrow0 = nb0; borrow1 = nb1;

        const int ob = l * 4;
        oadd[ob + 0] = make_float4(addr[0],  addr[1],  addr[2],  addr[3]);
        oadd[ob + 1] = make_float4(addr[4],  addr[5],  addr[6],  addr[7]);
        oadd[ob + 2] = make_float4(addr[8],  addr[9],  addr[10], addr[11]);
        oadd[ob + 3] = make_float4(addr[12], addr[13], addr[14], addr[15]);
        osub[ob + 0] = make_float4(subr[0],  subr[1],  subr[2],  subr[3]);
        osub[ob + 1] = make_float4(subr[4],  subr[5],  subr[6],  subr[7]);
        osub[ob + 2] = make_float4(subr[8],  subr[9],  subr[10], subr[11]);
        osub[ob + 3] = make_float4(subr[12], subr[13], subr[14], subr[15]);
    }
}

extern "C" void kernel_launch(void* const* d_in, const int* in_sizes, int n_in,
                              void* d_out, int out_size)
{
    const float* op1 = (const float*)d_in[0];
    const float* op2 = (const float*)d_in[1];
    // d_in[2..5] are the one-hot lookup tables; derived analytically, unused.
    float* out = (float*)d_out;

    bitop_kernel<<<BB / 128, 128>>>(op1, op2, out);
}